// round 9
// baseline (speedup 1.0000x reference)
#include <cuda_runtime.h>

// HungarianMatcher cost matrix: C[bs,nq,nt] =
//   5*L1(cxcywh) + 2*focal_class_cost(gathered by tgt_id) - 2*GIoU(xyxy)
//
// R8: ILP round. R3..R7 showed time pinned at ~39.5us while issue%, L1%, pipe%
// all float -> latency equilibrium, only more independent work per warp helps.
//  - 4 targets/thread (4-way ILP, STG.128) on two 640-target tiles + a
//    2-target tile for the remaining 320 (grid.y=3, exact coverage).
//  - single-RCP giou: (inter*ae + uni^2)/(uni*ae)  (one MUFU dep per pair)
//  - ta recomputed per pair (saves N registers/target set)

namespace {
constexpr int BS = 16, NQ = 900, NC = 91, NT = 1600;
constexpr int NROWS = BS * NQ;     // 14400
constexpr int TI = 20;             // query rows per block
constexpr int TPB = 160;           // 5 warps
}

__device__ float  g_cls2[NROWS * NC];   // 2*cost_class + 2
__device__ float4 g_qxyxy[NROWS];
__device__ float4 g_txyxy[NT];
__device__ int    g_tid[NT];

// Fused prep: class table (+2 fold) + box xyxy + id decode.
// tgt_ids is int64 in the reference; jax with x64 disabled materializes
// int32. Detect: for nonneg int64 < 2^31, every odd int32 word is 0.
// All detection reads stay within the int32 buffer size.
__global__ void prep_all(const float* __restrict__ logits,
                         const float* __restrict__ pred_boxes,
                         const float* __restrict__ tgt_boxes,
                         const int*   __restrict__ ids32) {
    int i = blockIdx.x * blockDim.x + threadIdx.x;
    if (i < NROWS * NC) {
        float x = logits[i];
        float p = __fdividef(1.0f, 1.0f + __expf(-x));
        float omp = 1.0f - p;
        float pos = 0.25f * omp * omp * (-__logf(p + 1e-8f));
        float neg = 0.75f * p * p * (-__logf(omp + 1e-8f));
        g_cls2[i] = 2.0f * (pos - neg) + 2.0f;   // +2 from -2*giou's (-1) term
    }
    if (i < NROWS + NT) {
        if (i < NROWS) {
            float4 b = reinterpret_cast<const float4*>(pred_boxes)[i];
            float4 xy;
            xy.x = b.x - 0.5f * b.z; xy.y = b.y - 0.5f * b.w;
            xy.z = b.x + 0.5f * b.z; xy.w = b.y + 0.5f * b.w;
            g_qxyxy[i] = xy;
        } else {
            int j = i - NROWS;
            float4 b = reinterpret_cast<const float4*>(tgt_boxes)[j];
            float4 xy;
            xy.x = b.x - 0.5f * b.z; xy.y = b.y - 0.5f * b.w;
            xy.z = b.x + 0.5f * b.z; xy.w = b.y + 0.5f * b.w;
            g_txyxy[j] = xy;
        }
    }
    if (i < NT) {
        bool is64 = true;
#pragma unroll
        for (int k = 1; k < 128; k += 2)
            is64 &= (ids32[k] == 0);
        g_tid[i] = is64 ? ids32[2 * i] : ids32[i];
    }
}

__device__ __forceinline__ float pair_cost(
    const float4 qxy, const float4 qc, const float qarea,
    const float4 txy, const float4 tc, const float cls2p)
{
    // L1 on cxcywh
    float bb = fabsf(qc.x - tc.x) + fabsf(qc.y - tc.y)
             + fabsf(qc.z - tc.z) + fabsf(qc.w - tc.w);
    // enclosing box; intersection via identity:
    //   min(q2,t2) - max(q1,t1) = (qw + tw) - ex
    float ex = fmaxf(qxy.z, txy.z) - fminf(qxy.x, txy.x);
    float ey = fmaxf(qxy.w, txy.w) - fminf(qxy.y, txy.y);
    float w  = fmaxf((qc.z + tc.z) - ex, 0.0f);
    float h  = fmaxf((qc.w + tc.w) - ey, 0.0f);
    float inter = w * h;
    float ta  = tc.z * tc.w;
    float uni = (qarea + ta) - inter;
    float ae  = ex * ey;
    // inter/uni + uni/ae = (inter*ae + uni^2) / (uni*ae): single RCP
    float num = fmaf(inter, ae, uni * uni);
    float r   = __fdividef(1.0f, uni * ae);
    float c   = fmaf(5.0f, bb, cls2p);
    return fmaf(-2.0f, num * r, c);
}

template <int NTGT>
__device__ __forceinline__ void run_tile(
    const float* __restrict__ tgt_boxes, float* __restrict__ out,
    const float* s_cls, const float4* s_qxy, const float4* s_qc,
    int r0, int j0)
{
    float4 txy[NTGT], tc[NTGT];
    int    id[NTGT];
#pragma unroll
    for (int u = 0; u < NTGT; ++u) {
        txy[u] = g_txyxy[j0 + u];
        tc[u]  = reinterpret_cast<const float4*>(tgt_boxes)[j0 + u];
        id[u]  = g_tid[j0 + u];
    }
    __syncthreads();

    float* orow = out + (size_t)r0 * NT + j0;

#pragma unroll
    for (int q = 0; q < TI; ++q) {
        const float4 qxy = s_qxy[q];
        const float4 qc  = s_qc[q];
        const float  qarea = qc.z * qc.w;
        float c[NTGT];
#pragma unroll
        for (int u = 0; u < NTGT; ++u)
            c[u] = pair_cost(qxy, qc, qarea, txy[u], tc[u], s_cls[q * NC + id[u]]);
        if (NTGT == 4) {
            *reinterpret_cast<float4*>(orow + (size_t)q * NT) =
                make_float4(c[0], c[1], c[2], c[3]);
        } else {
            *reinterpret_cast<float2*>(orow + (size_t)q * NT) =
                make_float2(c[0], c[1]);
        }
    }
}

__global__ void __launch_bounds__(TPB, 6)
cost_kernel(const float* __restrict__ pred_boxes,
            const float* __restrict__ tgt_boxes,
            float* __restrict__ out)
{
    __shared__ float  s_cls[TI * NC];   // 7.3 KB
    __shared__ float4 s_qxy[TI];
    __shared__ float4 s_qc[TI];

    const int t  = threadIdx.x;
    const int r0 = blockIdx.x * TI;

    for (int k = t; k < TI * NC; k += TPB)
        s_cls[k] = g_cls2[r0 * NC + k];
    if (t < TI) {
        s_qxy[t] = g_qxyxy[r0 + t];
        s_qc[t]  = reinterpret_cast<const float4*>(pred_boxes)[r0 + t];
    }
    // (run_tile does the __syncthreads after loading its target constants)

    if (blockIdx.y < 2) {
        // 4-target tiles: j in [0,640) and [640,1280)
        int j0 = blockIdx.y * 4 * TPB + 4 * t;
        run_tile<4>(tgt_boxes, out, s_cls, s_qxy, s_qc, r0, j0);
    } else {
        // 2-target tile: j in [1280,1600)
        int j0 = 1280 + 2 * t;
        run_tile<2>(tgt_boxes, out, s_cls, s_qxy, s_qc, r0, j0);
    }
}

extern "C" void kernel_launch(void* const* d_in, const int* in_sizes, int n_in,
                              void* d_out, int out_size) {
    const float* logits = (const float*)d_in[0];   // [16,900,91]
    const float* pboxes = (const float*)d_in[1];   // [16,900,4]
    const float* tboxes = (const float*)d_in[2];   // [1600,4]
    const int*   ids    = (const int*)d_in[3];     // [1600] (int32 or int64 view)
    float* out = (float*)d_out;                    // [16,900,1600]

    prep_all<<<(NROWS * NC + 255) / 256, 256>>>(logits, pboxes, tboxes, ids);
    dim3 grid(NROWS / TI, 3);
    cost_kernel<<<grid, TPB>>>(pboxes, tboxes, out);
}

// round 10
// speedup vs baseline: 1.1483x; 1.1483x over previous
#include <cuda_runtime.h>

// HungarianMatcher cost matrix: C[bs,nq,nt] =
//   5*L1(cxcywh) + 2*focal_class_cost(gathered by tgt_id) - 2*GIoU(xyxy)
//
// R9 = R7 skeleton (2 tgt/thread, TPB=160, TI=20, minblocks=9; best known) +
// shared-unit pressure cuts:
//  - single-RCP giou: inter/uni + uni/ae = (inter*ae + uni^2)/(uni*ae)
//    -> 1 MUFU per pair (was 2); MUFU rt=8/SMSP was ~33% occupied, bursty.
//  - class gathers via per-thread base pointer + compile-time immediate
//    offsets (LDS [Rp+imm]) -> no per-gather IMAD.

namespace {
constexpr int BS = 16, NQ = 900, NC = 91, NT = 1600;
constexpr int NROWS = BS * NQ;     // 14400
constexpr int TI = 20;             // query rows per block (14400 % 20 == 0)
constexpr int TPB = 160;           // 5 warps
constexpr int TGT_PER_BLK = 2 * TPB;       // 320
constexpr int NTILE_T = NT / TGT_PER_BLK;  // 5
}

__device__ float  g_cls2[NROWS * NC];   // 2*cost_class + 2
__device__ float4 g_qxyxy[NROWS];
__device__ float4 g_txyxy[NT];
__device__ float  g_tarea[NT];
__device__ int    g_tid[NT];

// Fused prep: class table (+2 fold) + box xyxy + target area + id decode.
// tgt_ids is int64 in the reference; jax with x64 disabled materializes
// int32. Detect: for nonneg int64 < 2^31, every odd int32 word is 0.
// All detection reads stay within the int32 buffer size.
__global__ void prep_all(const float* __restrict__ logits,
                         const float* __restrict__ pred_boxes,
                         const float* __restrict__ tgt_boxes,
                         const int*   __restrict__ ids32) {
    int i = blockIdx.x * blockDim.x + threadIdx.x;
    if (i < NROWS * NC) {
        float x = logits[i];
        float p = __fdividef(1.0f, 1.0f + __expf(-x));
        float omp = 1.0f - p;
        float pos = 0.25f * omp * omp * (-__logf(p + 1e-8f));
        float neg = 0.75f * p * p * (-__logf(omp + 1e-8f));
        g_cls2[i] = 2.0f * (pos - neg) + 2.0f;   // +2 from -2*giou's (-1) term
    }
    if (i < NROWS + NT) {
        if (i < NROWS) {
            float4 b = reinterpret_cast<const float4*>(pred_boxes)[i];
            float4 xy;
            xy.x = b.x - 0.5f * b.z; xy.y = b.y - 0.5f * b.w;
            xy.z = b.x + 0.5f * b.z; xy.w = b.y + 0.5f * b.w;
            g_qxyxy[i] = xy;
        } else {
            int j = i - NROWS;
            float4 b = reinterpret_cast<const float4*>(tgt_boxes)[j];
            float4 xy;
            xy.x = b.x - 0.5f * b.z; xy.y = b.y - 0.5f * b.w;
            xy.z = b.x + 0.5f * b.z; xy.w = b.y + 0.5f * b.w;
            g_txyxy[j] = xy;
            g_tarea[j] = b.z * b.w;
        }
    }
    if (i < NT) {
        bool is64 = true;
#pragma unroll
        for (int k = 1; k < 128; k += 2)
            is64 &= (ids32[k] == 0);
        g_tid[i] = is64 ? ids32[2 * i] : ids32[i];
    }
}

__device__ __forceinline__ float pair_cost(
    const float4 qxy, const float4 qc, const float qarea,
    const float4 txy, const float4 tc, const float tarea,
    const float cls2p)
{
    // L1 on cxcywh
    float bb = fabsf(qc.x - tc.x) + fabsf(qc.y - tc.y)
             + fabsf(qc.z - tc.z) + fabsf(qc.w - tc.w);
    // enclosing box; intersection via identity:
    //   min(q2,t2) - max(q1,t1) = (qw + tw) - ex
    float ex = fmaxf(qxy.z, txy.z) - fminf(qxy.x, txy.x);
    float ey = fmaxf(qxy.w, txy.w) - fminf(qxy.y, txy.y);
    float w  = fmaxf((qc.z + tc.z) - ex, 0.0f);
    float h  = fmaxf((qc.w + tc.w) - ey, 0.0f);
    float inter = w * h;
    float uni = (qarea + tarea) - inter;
    float ae  = ex * ey;
    // inter/uni + uni/ae = (inter*ae + uni^2) / (uni*ae): single RCP per pair
    float num = fmaf(inter, ae, uni * uni);
    float r   = __fdividef(1.0f, uni * ae);
    float c   = fmaf(5.0f, bb, cls2p);
    return fmaf(-2.0f, num * r, c);
}

__global__ void __launch_bounds__(TPB, 9)
cost_kernel(const float* __restrict__ pred_boxes,
            const float* __restrict__ tgt_boxes,
            float* __restrict__ out)
{
    __shared__ float  s_cls[TI * NC];   // 7.3 KB
    __shared__ float4 s_qxy[TI];
    __shared__ float4 s_qc[TI];

    const int t  = threadIdx.x;
    const int r0 = blockIdx.x * TI;
    const int j0 = blockIdx.y * TGT_PER_BLK + 2 * t;

    for (int k = t; k < TI * NC; k += TPB)
        s_cls[k] = g_cls2[r0 * NC + k];
    if (t < TI) {
        s_qxy[t] = g_qxyxy[r0 + t];
        s_qc[t]  = reinterpret_cast<const float4*>(pred_boxes)[r0 + t];
    }

    // per-thread target constants (registers; must stay resident — see R5)
    const float4 t0xy = g_txyxy[j0];
    const float4 t1xy = g_txyxy[j0 + 1];
    const float  t0a  = g_tarea[j0];
    const float  t1a  = g_tarea[j0 + 1];
    const float4 t0c  = reinterpret_cast<const float4*>(tgt_boxes)[j0];
    const float4 t1c  = reinterpret_cast<const float4*>(tgt_boxes)[j0 + 1];
    const int id0 = g_tid[j0];
    const int id1 = g_tid[j0 + 1];
    __syncthreads();

    // hoisted gather bases: per-q access is [imm] off these
    const float* p0 = s_cls + id0;
    const float* p1 = s_cls + id1;

    float* orow = out + (size_t)r0 * NT + j0;

#pragma unroll
    for (int q = 0; q < TI; ++q) {
        const float4 qxy = s_qxy[q];
        const float4 qc  = s_qc[q];
        const float  qarea = qc.z * qc.w;        // hoisted once per q
        float c0 = pair_cost(qxy, qc, qarea, t0xy, t0c, t0a, p0[q * NC]);
        float c1 = pair_cost(qxy, qc, qarea, t1xy, t1c, t1a, p1[q * NC]);
        *reinterpret_cast<float2*>(orow + (size_t)q * NT) = make_float2(c0, c1);
    }
}

extern "C" void kernel_launch(void* const* d_in, const int* in_sizes, int n_in,
                              void* d_out, int out_size) {
    const float* logits = (const float*)d_in[0];   // [16,900,91]
    const float* pboxes = (const float*)d_in[1];   // [16,900,4]
    const float* tboxes = (const float*)d_in[2];   // [1600,4]
    const int*   ids    = (const int*)d_in[3];     // [1600] (int32 or int64 view)
    float* out = (float*)d_out;                    // [16,900,1600]

    prep_all<<<(NROWS * NC + 255) / 256, 256>>>(logits, pboxes, tboxes, ids);
    dim3 grid(NROWS / TI, NTILE_T);
    cost_kernel<<<grid, TPB>>>(pboxes, tboxes, out);
}